// round 1
// baseline (speedup 1.0000x reference)
#include <cuda_runtime.h>

// ---------------------------------------------------------------------------
// WaveConv2d via the perfect-reconstruction identity:
//   out = x + IDWT( mix(level4 coeffs) - level4 coeffs, zeros elsewhere )
// Only the lowpass analysis chain + level-4 split + tiny mix + lowpass
// synthesis chain are computed. All scratch in static __device__ arrays.
// ---------------------------------------------------------------------------

__constant__ float F_H[12] = {
    0.11154074335008017f,  0.4946238903983854f,   0.7511339080215775f,
    0.3152503517092432f,  -0.22626469396516913f, -0.12976686756709563f,
    0.09750160558707936f,  0.02752286553001629f, -0.031582039318031156f,
    0.0005538422009938016f, 0.004777257511010651f, -0.00107730108499558f};

// scratch buffers (sizes in floats)
__device__ float gA[34340864];   // 256*512*262
__device__ float gB[17572864];   // 256*262*262
__device__ float gC[9121792];    // 256*262*136
__device__ float gD[4734976];    // 256*136*136
__device__ float gE[2541568];    // 256*136*73
__device__ float gF[1401856];    // 256*74*74
__device__ float gG1[795648];    // 256*74*42
__device__ float gG2[795648];
__device__ float gLL[451584], gLH[451584], gHL[451584], gHH[451584]; // 256*42*42
__device__ float gML[451584], gMLH[451584], gMHL[451584], gMHH[451584];

__device__ __forceinline__ int refl(int i, int N) {
    if (i < 0) i = -1 - i;
    if (i >= N) i = 2 * N - 1 - i;
    return i;
}

// ---------------- analysis (lowpass) along width: in (rows,N) -> out (rows,No)
__global__ void anaW_lo(const float* __restrict__ in, float* __restrict__ out,
                        long rows, int N, int No, int left) {
    long idx = blockIdx.x * (long)blockDim.x + threadIdx.x;
    long total = rows * (long)No;
    if (idx >= total) return;
    int t = (int)(idx % No);
    long r = idx / No;
    const float* ip = in + r * (long)N;
    int base = 2 * t - left;
    float acc = 0.f;
#pragma unroll
    for (int j = 0; j < 12; j++) acc += F_H[j] * ip[refl(base + j, N)];
    out[idx] = acc;
}

// analysis (lowpass) along height: in (C,H,W) -> out (C,Ho,W)
__global__ void anaH_lo(const float* __restrict__ in, float* __restrict__ out,
                        int C, int H, int W, int Ho, int left) {
    long idx = blockIdx.x * (long)blockDim.x + threadIdx.x;
    long total = (long)C * Ho * W;
    if (idx >= total) return;
    int w = (int)(idx % W);
    long tmp = idx / W;
    int t = (int)(tmp % Ho);
    int c = (int)(tmp / Ho);
    const float* ip = in + (long)c * H * W + w;
    int base = 2 * t - left;
    float acc = 0.f;
#pragma unroll
    for (int j = 0; j < 12; j++) acc += F_H[j] * ip[(long)refl(base + j, H) * W];
    out[idx] = acc;
}

// analysis (lo + hi) along width
__global__ void anaW_both(const float* __restrict__ in, float* __restrict__ olo,
                          float* __restrict__ ohi, long rows, int N, int No, int left) {
    long idx = blockIdx.x * (long)blockDim.x + threadIdx.x;
    long total = rows * (long)No;
    if (idx >= total) return;
    int t = (int)(idx % No);
    long r = idx / No;
    const float* ip = in + r * (long)N;
    int base = 2 * t - left;
    float alo = 0.f, ahi = 0.f;
#pragma unroll
    for (int j = 0; j < 12; j++) {
        float v = ip[refl(base + j, N)];
        alo += F_H[j] * v;
        float hj = (j & 1) ? -F_H[11 - j] : F_H[11 - j];
        ahi += hj * v;
    }
    olo[idx] = alo;
    ohi[idx] = ahi;
}

// analysis (lo + hi) along height
__global__ void anaH_both(const float* __restrict__ in, float* __restrict__ olo,
                          float* __restrict__ ohi, int C, int H, int W, int Ho, int left) {
    long idx = blockIdx.x * (long)blockDim.x + threadIdx.x;
    long total = (long)C * Ho * W;
    if (idx >= total) return;
    int w = (int)(idx % W);
    long tmp = idx / W;
    int t = (int)(tmp % Ho);
    int c = (int)(tmp / Ho);
    const float* ip = in + (long)c * H * W + w;
    int base = 2 * t - left;
    float alo = 0.f, ahi = 0.f;
#pragma unroll
    for (int j = 0; j < 12; j++) {
        float v = ip[(long)refl(base + j, H) * W];
        alo += F_H[j] * v;
        float hj = (j & 1) ? -F_H[11 - j] : F_H[11 - j];
        ahi += hj * v;
    }
    olo[idx] = alo;
    ohi[idx] = ahi;
}

// ---------------- per-pixel channel mix minus identity on a 42x42 subband
// in/out: (8 b, 32 ch, 1764 px) fp32.  w index: (i*32+o)*ioStride + px
__global__ void mixK(const float* __restrict__ in, const float* __restrict__ w,
                     float* __restrict__ out, long ioStride) {
    int p = blockIdx.x * blockDim.x + threadIdx.x;
    if (p >= 1764) return;
    for (int o = 0; o < 32; o++) {
        float acc[8];
#pragma unroll
        for (int b = 0; b < 8; b++) acc[b] = -in[((long)b * 32 + o) * 1764 + p];
        for (int i = 0; i < 32; i++) {
            float wv = w[((long)i * 32 + o) * ioStride + p];
#pragma unroll
            for (int b = 0; b < 8; b++) acc[b] += in[((long)b * 32 + i) * 1764 + p] * wv;
        }
#pragma unroll
        for (int b = 0; b < 8; b++) out[((long)b * 32 + o) * 1764 + p] = acc[b];
    }
}

// ---------------- synthesis (lo + hi bands) along height: in (C,N,W) -> out (C,M,W)
__global__ void syn2H(const float* __restrict__ lo, const float* __restrict__ hi,
                      float* __restrict__ out, int C, int N, int W, int M) {
    long idx = blockIdx.x * (long)blockDim.x + threadIdx.x;
    long total = (long)C * M * W;
    if (idx >= total) return;
    int w = (int)(idx % W);
    long tmp = idx / W;
    int t = (int)(tmp % M);
    int c = (int)(tmp / M);
    const float* lp = lo + (long)c * N * W + w;
    const float* hp = hi + (long)c * N * W + w;
    float acc = 0.f;
#pragma unroll
    for (int j = 0; j < 12; j++) {
        int u = t + j - 1;
        if (u & 1) continue;         // need even dilated position (also kills u==-1)
        int m = u >> 1;
        if (m >= N) continue;
        float sl = F_H[11 - j];
        float sh = (j & 1) ? F_H[j] : -F_H[j];
        acc += sl * lp[(long)m * W] + sh * hp[(long)m * W];
    }
    out[idx] = acc;
}

// synthesis (lo + hi) along width: in (rows,N) -> out (rows,M)
__global__ void syn2W(const float* __restrict__ lo, const float* __restrict__ hi,
                      float* __restrict__ out, long rows, int N, int M) {
    long idx = blockIdx.x * (long)blockDim.x + threadIdx.x;
    long total = rows * (long)M;
    if (idx >= total) return;
    int t = (int)(idx % M);
    long r = idx / M;
    const float* lp = lo + r * (long)N;
    const float* hp = hi + r * (long)N;
    float acc = 0.f;
#pragma unroll
    for (int j = 0; j < 12; j++) {
        int u = t + j - 1;
        if (u & 1) continue;
        int m = u >> 1;
        if (m >= N) continue;
        float sl = F_H[11 - j];
        float sh = (j & 1) ? F_H[j] : -F_H[j];
        acc += sl * lp[m] + sh * hp[m];
    }
    out[idx] = acc;
}

// synthesis (lowpass only) along height, strided input (supports crop reads)
__global__ void synloH(const float* __restrict__ in, float* __restrict__ out,
                       int C, int N, int W, int M, long inRowStride, long inChanStride) {
    long idx = blockIdx.x * (long)blockDim.x + threadIdx.x;
    long total = (long)C * M * W;
    if (idx >= total) return;
    int w = (int)(idx % W);
    long tmp = idx / W;
    int t = (int)(tmp % M);
    int c = (int)(tmp / M);
    const float* ip = in + (long)c * inChanStride + w;
    float acc = 0.f;
#pragma unroll
    for (int j = 0; j < 12; j++) {
        int u = t + j - 1;
        if (u & 1) continue;
        int m = u >> 1;
        if (m >= N) continue;
        acc += F_H[11 - j] * ip[(long)m * inRowStride];
    }
    out[idx] = acc;
}

// synthesis (lowpass only) along width, strided input
__global__ void synloW(const float* __restrict__ in, float* __restrict__ out,
                       long rows, int N, int M, long inRowStride) {
    long idx = blockIdx.x * (long)blockDim.x + threadIdx.x;
    long total = rows * (long)M;
    if (idx >= total) return;
    int t = (int)(idx % M);
    long r = idx / M;
    const float* ip = in + r * inRowStride;
    float acc = 0.f;
#pragma unroll
    for (int j = 0; j < 12; j++) {
        int u = t + j - 1;
        if (u & 1) continue;
        int m = u >> 1;
        if (m >= N) continue;
        acc += F_H[11 - j] * ip[m];
    }
    out[idx] = acc;
}

// final: lowpass width synthesis fused with +x, writes d_out
__global__ void synloW_add(const float* __restrict__ in, const float* __restrict__ x,
                           float* __restrict__ out, long rows, int N, int M,
                           long inRowStride) {
    long idx = blockIdx.x * (long)blockDim.x + threadIdx.x;
    long total = rows * (long)M;
    if (idx >= total) return;
    int t = (int)(idx % M);
    long r = idx / M;
    const float* ip = in + r * inRowStride;
    float acc = 0.f;
#pragma unroll
    for (int j = 0; j < 12; j++) {
        int u = t + j - 1;
        if (u & 1) continue;
        int m = u >> 1;
        if (m >= N) continue;
        acc += F_H[11 - j] * ip[m];
    }
    out[idx] = x[idx] + acc;
}

static inline int gridFor(long n, int tb) { return (int)((n + tb - 1) / tb); }

extern "C" void kernel_launch(void* const* d_in, const int* in_sizes, int n_in,
                              void* d_out, int out_size) {
    (void)in_sizes; (void)n_in; (void)out_size;
    const float* x   = (const float*)d_in[0];   // (8,32,512,512)
    const float* wyl = (const float*)d_in[1];   // (32,32,42,42)
    const float* wyh = (const float*)d_in[2];   // (32,32,3,42,42)
    float* out = (float*)d_out;                 // (8,32,512,512)

    float *A,*B,*C,*D,*E,*F,*G1,*G2,*LL,*LH,*HL,*HH,*ML,*MLH,*MHL,*MHH;
    cudaGetSymbolAddress((void**)&A,  gA);
    cudaGetSymbolAddress((void**)&B,  gB);
    cudaGetSymbolAddress((void**)&C,  gC);
    cudaGetSymbolAddress((void**)&D,  gD);
    cudaGetSymbolAddress((void**)&E,  gE);
    cudaGetSymbolAddress((void**)&F,  gF);
    cudaGetSymbolAddress((void**)&G1, gG1);
    cudaGetSymbolAddress((void**)&G2, gG2);
    cudaGetSymbolAddress((void**)&LL, gLL);
    cudaGetSymbolAddress((void**)&LH, gLH);
    cudaGetSymbolAddress((void**)&HL, gHL);
    cudaGetSymbolAddress((void**)&HH, gHH);
    cudaGetSymbolAddress((void**)&ML, gML);
    cudaGetSymbolAddress((void**)&MLH, gMLH);
    cudaGetSymbolAddress((void**)&MHL, gMHL);
    cudaGetSymbolAddress((void**)&MHH, gMHH);

    const int TB = 256;

    // -------- forward lowpass chain (all analysis pads have left=10) --------
    // L1: x (256,512,512) -w-> A (256,512,261) -h-> B (256,261,261)
    anaW_lo<<<gridFor(256L*512*261, TB), TB>>>(x, A, 256L*512, 512, 261, 10);
    anaH_lo<<<gridFor(256L*261*261, TB), TB>>>(A, B, 256, 512, 261, 261, 10);
    // L2: B -w-> C (256,261,136) -h-> D (256,136,136)
    anaW_lo<<<gridFor(256L*261*136, TB), TB>>>(B, C, 256L*261, 261, 136, 10);
    anaH_lo<<<gridFor(256L*136*136, TB), TB>>>(C, D, 256, 261, 136, 136, 10);
    // L3: D -w-> E (256,136,73) -h-> F (256,73,73)
    anaW_lo<<<gridFor(256L*136*73, TB), TB>>>(D, E, 256L*136, 136, 73, 10);
    anaH_lo<<<gridFor(256L*73*73, TB), TB>>>(E, F, 256, 136, 73, 73, 10);
    // L4 full split: F -w-> (G1 lo, G2 hi) (256,73,42); -h-> 4 subbands (256,42,42)
    anaW_both<<<gridFor(256L*73*42, TB), TB>>>(F, G1, G2, 256L*73, 73, 42, 10);
    anaH_both<<<gridFor(256L*42*42, TB), TB>>>(G1, LL, LH, 256, 73, 42, 42, 10);
    anaH_both<<<gridFor(256L*42*42, TB), TB>>>(G2, HL, HH, 256, 73, 42, 42, 10);

    // -------- per-pixel channel mix minus identity (deltas) --------
    mixK<<<14, 128>>>(LL, wyl,              ML,  1764);
    mixK<<<14, 128>>>(LH, wyh + 0 * 1764,   MLH, 5292);
    mixK<<<14, 128>>>(HL, wyh + 1 * 1764,   MHL, 5292);
    mixK<<<14, 128>>>(HH, wyh + 2 * 1764,   MHH, 5292);

    // -------- inverse --------
    // L4 full synthesis: (ML,MLH) -h-> G1 (256,74,42); (MHL,MHH) -h-> G2; -w-> F (256,74,74)
    syn2H<<<gridFor(256L*74*42, TB), TB>>>(ML,  MLH, G1, 256, 42, 42, 74);
    syn2H<<<gridFor(256L*74*42, TB), TB>>>(MHL, MHH, G2, 256, 42, 42, 74);
    syn2W<<<gridFor(256L*74*74, TB), TB>>>(G1, G2, F, 256L*74, 42, 74);
    // L3 (zero H-bands => lowpass only), crop 74->73 via strided read
    synloH<<<gridFor(256L*136*73, TB), TB>>>(F, E, 256, 73, 73, 136, 74, 74L*74);
    synloW<<<gridFor(256L*136*136, TB), TB>>>(E, D, 256L*136, 73, 136, 73);
    // L2: D (256,136,136) -> C (256,262,136) -> B (256,262,262)
    synloH<<<gridFor(256L*262*136, TB), TB>>>(D, C, 256, 136, 136, 262, 136, 136L*136);
    synloW<<<gridFor(256L*262*262, TB), TB>>>(C, B, 256L*262, 136, 262, 136);
    // L1: crop 262->261, B -> A (256,512,261) -> out = x + synthesis (256,512,512)
    synloH<<<gridFor(256L*512*261, TB), TB>>>(B, A, 256, 261, 261, 512, 262, 262L*262);
    synloW_add<<<gridFor(256L*512*512, TB), TB>>>(A, x, out, 256L*512, 261, 512, 261);
}

// round 3
// speedup vs baseline: 4.6117x; 4.6117x over previous
#include <cuda_runtime.h>

// ---------------------------------------------------------------------------
// WaveConv2d via the perfect-reconstruction identity:
//   out = x + IDWT( mix(level4 coeffs) - level4 coeffs, zeros elsewhere )
// Round 3: Round-2 fused kernels with CORRECTED synthesis coefficient table.
// ---------------------------------------------------------------------------

__constant__ float F_H[12] = {
    0.11154074335008017f,  0.4946238903983854f,   0.7511339080215775f,
    0.3152503517092432f,  -0.22626469396516913f, -0.12976686756709563f,
    0.09750160558707936f,  0.02752286553001629f, -0.031582039318031156f,
    0.0005538422009938016f, 0.004777257511010651f, -0.00107730108499558f};

// Synthesis lowpass coeffs by output parity: 6 taps each.
// even t: F_H[10-2k], odd t: F_H[11-2k], k = 0..5
__constant__ float SYN_C[2][6] = {
    {0.004777257511010651f, -0.031582039318031156f, 0.09750160558707936f,
     -0.22626469396516913f,  0.7511339080215775f,   0.11154074335008017f},
    {-0.00107730108499558f, 0.0005538422009938016f, 0.02752286553001629f,
     -0.12976686756709563f,  0.3152503517092432f,   0.4946238903983854f}};

// scratch buffers (sizes in floats)
__device__ float gB[17572864];   // 256*262*262
__device__ float gD[4734976];    // 256*136*136
__device__ float gE[2541568];    // 256*73*73 compact fits
__device__ float gF[1401856];    // 256*74*74
__device__ float gG1[795648];    // 256*74*42
__device__ float gG2[795648];
__device__ float gLL[451584], gLH[451584], gHL[451584], gHH[451584];
__device__ float gML[451584], gMLH[451584], gMHL[451584], gMHH[451584];

__device__ __forceinline__ int refl(int i, int N) {
    if (i < 0) i = -1 - i;
    if (i >= N) i = 2 * N - 1 - i;
    return i;
}

// ---------------------------------------------------------------------------
// Fused one-level lowpass analysis: in (C,N,N) -> out (C,No,No).
// Output tile 32x32, input tile 84x84 (refl-padded at load).
// ---------------------------------------------------------------------------
__global__ void fusedAna(const float* __restrict__ in, float* __restrict__ out,
                         int N, int No) {
    __shared__ float sIn[84][85];
    __shared__ float sMid[84][33];
    const int c0 = blockIdx.x * 32;
    const int t0 = blockIdx.y * 32;
    const int ch = blockIdx.z;
    const float* ip = in + (long)ch * N * N;

    for (int idx = threadIdx.x; idx < 84 * 84; idx += blockDim.x) {
        int qi = idx / 84, ci = idx % 84;
        int gr = refl(2 * t0 - 10 + qi, N);
        int gc = refl(2 * c0 - 10 + ci, N);
        sIn[qi][ci] = ip[(long)gr * N + gc];
    }
    __syncthreads();

    for (int idx = threadIdx.x; idx < 84 * 32; idx += blockDim.x) {
        int qi = idx / 32, ci = idx % 32;
        if (c0 + ci < No) {
            float acc = 0.f;
#pragma unroll
            for (int j = 0; j < 12; j++) acc += F_H[j] * sIn[qi][2 * ci + j];
            sMid[qi][ci] = acc;
        }
    }
    __syncthreads();

    for (int idx = threadIdx.x; idx < 32 * 32; idx += blockDim.x) {
        int ti = idx / 32, ci = idx % 32;
        int t = t0 + ti, c = c0 + ci;
        if (t < No && c < No) {
            float acc = 0.f;
#pragma unroll
            for (int j = 0; j < 12; j++) acc += F_H[j] * sMid[2 * ti + j][ci];
            out[(long)ch * No * No + (long)t * No + c] = acc;
        }
    }
}

// ---------------------------------------------------------------------------
// Fused one-level lowpass synthesis: in (C,N,N) strides (rs, cs) -> (C,M,M),
// M = 2N-10. Optional fused +x. Output tile 64x64, input 37x37 zero-padded.
// ---------------------------------------------------------------------------
__global__ void fusedSyn(const float* __restrict__ in, float* __restrict__ out,
                         const float* __restrict__ x,
                         int N, long rs, long cs, int M) {
    __shared__ float sIn[37][38];
    __shared__ float sMid[64][38];
    const int c0 = blockIdx.x * 64;
    const int r0 = blockIdx.y * 64;
    const int ch = blockIdx.z;
    const int q0 = r0 >> 1, m0 = c0 >> 1;
    const float* ip = in + (long)ch * cs;

    for (int idx = threadIdx.x; idx < 37 * 37; idx += blockDim.x) {
        int qi = idx / 37, mi = idx % 37;
        int q = q0 + qi, m = m0 + mi;
        sIn[qi][mi] = (q < N && m < N) ? ip[(long)q * rs + m] : 0.f;
    }
    __syncthreads();

    for (int idx = threadIdx.x; idx < 64 * 37; idx += blockDim.x) {
        int ri = idx / 37, mi = idx % 37;
        const float* cf = SYN_C[(r0 + ri) & 1];
        int qb = ri >> 1;
        float acc = 0.f;
#pragma unroll
        for (int k = 0; k < 6; k++) acc += cf[k] * sIn[qb + k][mi];
        sMid[ri][mi] = acc;
    }
    __syncthreads();

    for (int idx = threadIdx.x; idx < 64 * 64; idx += blockDim.x) {
        int ti = idx / 64, ci = idx % 64;
        int r = r0 + ti, c = c0 + ci;
        if (r < M && c < M) {
            const float* cf = SYN_C[c & 1];
            int mb = ci >> 1;
            float acc = 0.f;
#pragma unroll
            for (int k = 0; k < 6; k++) acc += cf[k] * sMid[ti][mb + k];
            long o = (long)ch * M * M + (long)r * M + c;
            out[o] = x ? (acc + x[o]) : acc;
        }
    }
}

// ---------------- L4 analysis (lo + hi) along width
__global__ void anaW_both(const float* __restrict__ in, float* __restrict__ olo,
                          float* __restrict__ ohi, long rows, int N, int No, int left) {
    long idx = blockIdx.x * (long)blockDim.x + threadIdx.x;
    long total = rows * (long)No;
    if (idx >= total) return;
    int t = (int)(idx % No);
    long r = idx / No;
    const float* ip = in + r * (long)N;
    int base = 2 * t - left;
    float alo = 0.f, ahi = 0.f;
#pragma unroll
    for (int j = 0; j < 12; j++) {
        float v = ip[refl(base + j, N)];
        alo += F_H[j] * v;
        float hj = (j & 1) ? -F_H[11 - j] : F_H[11 - j];
        ahi += hj * v;
    }
    olo[idx] = alo;
    ohi[idx] = ahi;
}

// L4 analysis (lo + hi) along height
__global__ void anaH_both(const float* __restrict__ in, float* __restrict__ olo,
                          float* __restrict__ ohi, int C, int H, int W, int Ho, int left) {
    long idx = blockIdx.x * (long)blockDim.x + threadIdx.x;
    long total = (long)C * Ho * W;
    if (idx >= total) return;
    int w = (int)(idx % W);
    long tmp = idx / W;
    int t = (int)(tmp % Ho);
    int c = (int)(tmp / Ho);
    const float* ip = in + (long)c * H * W + w;
    int base = 2 * t - left;
    float alo = 0.f, ahi = 0.f;
#pragma unroll
    for (int j = 0; j < 12; j++) {
        float v = ip[(long)refl(base + j, H) * W];
        alo += F_H[j] * v;
        float hj = (j & 1) ? -F_H[11 - j] : F_H[11 - j];
        ahi += hj * v;
    }
    olo[idx] = alo;
    ohi[idx] = ahi;
}

// ---------------- per-pixel channel mix minus identity on a 42x42 subband
__global__ void mixK2(const float* __restrict__ in, const float* __restrict__ w,
                      float* __restrict__ out, long ioStride) {
    int b = blockIdx.x >> 5, o = blockIdx.x & 31;
    for (int p = threadIdx.x; p < 1764; p += blockDim.x) {
        float acc = -in[((long)b * 32 + o) * 1764 + p];
        for (int i = 0; i < 32; i++)
            acc += in[((long)b * 32 + i) * 1764 + p] *
                   __ldg(&w[((long)i * 32 + o) * ioStride + p]);
        out[((long)b * 32 + o) * 1764 + p] = acc;
    }
}

// ---------------- L4 synthesis (lo + hi bands) along height
__global__ void syn2H(const float* __restrict__ lo, const float* __restrict__ hi,
                      float* __restrict__ out, int C, int N, int W, int M) {
    long idx = blockIdx.x * (long)blockDim.x + threadIdx.x;
    long total = (long)C * M * W;
    if (idx >= total) return;
    int w = (int)(idx % W);
    long tmp = idx / W;
    int t = (int)(tmp % M);
    int c = (int)(tmp / M);
    const float* lp = lo + (long)c * N * W + w;
    const float* hp = hi + (long)c * N * W + w;
    float acc = 0.f;
#pragma unroll
    for (int j = 0; j < 12; j++) {
        int u = t + j - 1;
        if (u & 1) continue;
        int m = u >> 1;
        if (m >= N) continue;
        float sl = F_H[11 - j];
        float sh = (j & 1) ? F_H[j] : -F_H[j];
        acc += sl * lp[(long)m * W] + sh * hp[(long)m * W];
    }
    out[idx] = acc;
}

// L4 synthesis (lo + hi) along width
__global__ void syn2W(const float* __restrict__ lo, const float* __restrict__ hi,
                      float* __restrict__ out, long rows, int N, int M) {
    long idx = blockIdx.x * (long)blockDim.x + threadIdx.x;
    long total = rows * (long)M;
    if (idx >= total) return;
    int t = (int)(idx % M);
    long r = idx / M;
    const float* lp = lo + r * (long)N;
    const float* hp = hi + r * (long)N;
    float acc = 0.f;
#pragma unroll
    for (int j = 0; j < 12; j++) {
        int u = t + j - 1;
        if (u & 1) continue;
        int m = u >> 1;
        if (m >= N) continue;
        float sl = F_H[11 - j];
        float sh = (j & 1) ? F_H[j] : -F_H[j];
        acc += sl * lp[m] + sh * hp[m];
    }
    out[idx] = acc;
}

static inline int gridFor(long n, int tb) { return (int)((n + tb - 1) / tb); }
static inline int ceilDiv(int a, int b) { return (a + b - 1) / b; }

extern "C" void kernel_launch(void* const* d_in, const int* in_sizes, int n_in,
                              void* d_out, int out_size) {
    (void)in_sizes; (void)n_in; (void)out_size;
    const float* x   = (const float*)d_in[0];
    const float* wyl = (const float*)d_in[1];
    const float* wyh = (const float*)d_in[2];
    float* out = (float*)d_out;

    float *B,*D,*E,*F,*G1,*G2,*LL,*LH,*HL,*HH,*ML,*MLH,*MHL,*MHH;
    cudaGetSymbolAddress((void**)&B,  gB);
    cudaGetSymbolAddress((void**)&D,  gD);
    cudaGetSymbolAddress((void**)&E,  gE);
    cudaGetSymbolAddress((void**)&F,  gF);
    cudaGetSymbolAddress((void**)&G1, gG1);
    cudaGetSymbolAddress((void**)&G2, gG2);
    cudaGetSymbolAddress((void**)&LL, gLL);
    cudaGetSymbolAddress((void**)&LH, gLH);
    cudaGetSymbolAddress((void**)&HL, gHL);
    cudaGetSymbolAddress((void**)&HH, gHH);
    cudaGetSymbolAddress((void**)&ML, gML);
    cudaGetSymbolAddress((void**)&MLH, gMLH);
    cudaGetSymbolAddress((void**)&MHL, gMHL);
    cudaGetSymbolAddress((void**)&MHH, gMHH);

    const int TB = 256;

    // forward lowpass chain (fused 2D per level)
    fusedAna<<<dim3(ceilDiv(261, 32), ceilDiv(261, 32), 256), 256>>>(x, B, 512, 261);
    fusedAna<<<dim3(ceilDiv(136, 32), ceilDiv(136, 32), 256), 256>>>(B, D, 261, 136);
    fusedAna<<<dim3(ceilDiv(73, 32), ceilDiv(73, 32), 256), 256>>>(D, E, 136, 73);
    // L4 full split
    anaW_both<<<gridFor(256L * 73 * 42, TB), TB>>>(E, G1, G2, 256L * 73, 73, 42, 10);
    anaH_both<<<gridFor(256L * 42 * 42, TB), TB>>>(G1, LL, LH, 256, 73, 42, 42, 10);
    anaH_both<<<gridFor(256L * 42 * 42, TB), TB>>>(G2, HL, HH, 256, 73, 42, 42, 10);

    // channel mix minus identity
    mixK2<<<256, 256>>>(LL, wyl,            ML,  1764);
    mixK2<<<256, 256>>>(LH, wyh + 0 * 1764, MLH, 5292);
    mixK2<<<256, 256>>>(HL, wyh + 1 * 1764, MHL, 5292);
    mixK2<<<256, 256>>>(HH, wyh + 2 * 1764, MHH, 5292);

    // inverse
    syn2H<<<gridFor(256L * 74 * 42, TB), TB>>>(ML,  MLH, G1, 256, 42, 42, 74);
    syn2H<<<gridFor(256L * 74 * 42, TB), TB>>>(MHL, MHH, G2, 256, 42, 42, 74);
    syn2W<<<gridFor(256L * 74 * 74, TB), TB>>>(G1, G2, F, 256L * 74, 42, 74);
    fusedSyn<<<dim3(ceilDiv(136, 64), ceilDiv(136, 64), 256), 256>>>(
        F, D, nullptr, 73, 74, 74L * 74, 136);
    fusedSyn<<<dim3(ceilDiv(262, 64), ceilDiv(262, 64), 256), 256>>>(
        D, B, nullptr, 136, 136, 136L * 136, 262);
    fusedSyn<<<dim3(ceilDiv(512, 64), ceilDiv(512, 64), 256), 256>>>(
        B, out, x, 261, 262, 262L * 262, 512);
}